// round 5
// baseline (speedup 1.0000x reference)
#include <cuda_runtime.h>
#include <cstdint>

// ExodusNeuron scan, R5: kill SMSP co-location.
// 128 blocks x 64 threads (2 warps): 1 block per SM, warps on SMSP0/SMSP1
// (wid%4 mapping) -> every warp owns a scheduler. Warps fully independent:
// private smem ring (3 stages x 8KB), private cp.async groups, __syncwarp only.
// VEC=2 (float2) per thread; per-element numerics bit-exact vs reference:
//   xi = x*w ; vs = fma(a,vs,xi) ; vmp = fma(a,vm,vs)
//   spk = vmp >= 1 ; vm = spk ? vmp-1 : vmp

#define T_STEPS 2048
#define N_DIM   512
#define WARPS   2
#define BLOCK   (WARPS * 32)
#define VEC     2
#define NSEQ_W  64                      // sequences per warp
#define U       32                      // time-steps per tile
#define NT      (T_STEPS / U)           // 64 tiles
#define STAGES  3
#define TILE_FLOATS (U * NSEQ_W)        // 2048 floats = 8 KB
#define TILE_BYTES  (TILE_FLOATS * 4)
#define WARP_SMEM   (STAGES * TILE_FLOATS)

__device__ __forceinline__ void cp_async16(uint32_t saddr, const void* gaddr) {
    asm volatile("cp.async.cg.shared.global [%0], [%1], 16;\n"
                 :: "r"(saddr), "l"(gaddr));
}
__device__ __forceinline__ void cp_commit() {
    asm volatile("cp.async.commit_group;\n" ::: "memory");
}

__global__ __launch_bounds__(BLOCK)
void exodus_kernel(const float* __restrict__ x,
                   const float* __restrict__ w,
                   float* __restrict__ out) {
    __shared__ float smem[WARPS * WARP_SMEM];       // 48 KB exactly

    const int tid  = threadIdx.x;
    const int wid  = tid >> 5;
    const int lane = tid & 31;

    const int b  = blockIdx.x >> 2;                        // 32 batches
    const int n0 = (blockIdx.x & 3) * 128 + wid * NSEQ_W;  // warp's 64 seqs

    const float weight = w[0];
    const float alpha  = 0.95122942450071400910f;   // exp(-1/20) as f32

    const long gbase = (long)b * (T_STEPS * N_DIM) + n0;
    const float* __restrict__ xblk = x + gbase;
    float2* __restrict__ oplane = (float2*)(out + gbase) + lane;

    float* const wsm = smem + wid * WARP_SMEM;
    const uint32_t sbase = (uint32_t)__cvta_generic_to_shared(wsm);

    // Loader: row (time-step) = 64 floats = 256 B = 16 x 16 B chunks.
    // chunkCol = lane & 15 spans a row; rowOff = lane >> 4 staggers 2 rows.
    const int chunkCol = lane & 15;
    const int rowOff   = lane >> 4;

    auto issue_tile = [&](int tt) {
        const uint32_t s0 = sbase + (tt % STAGES) * TILE_BYTES
                          + rowOff * 256 + chunkCol * 16;
        const float* g0 = xblk + (long)(tt * U + rowOff) * N_DIM + chunkCol * 4;
        #pragma unroll
        for (int i = 0; i < U / 2; i++)                 // 16 x LDGSTS.128
            cp_async16(s0 + i * 2 * 256, g0 + (long)i * 2 * N_DIM);
        cp_commit();
    };

    issue_tile(0);
    issue_tile(1);

    float vs0 = 0.0f, vm0 = 0.0f;
    float vs1 = 0.0f, vm1 = 0.0f;

    for (int tt = 0; tt < NT; tt++) {
        if (tt + 2 < NT) issue_tile(tt + 2);

        const int rem = NT - 1 - tt;
        if      (rem >= 2) asm volatile("cp.async.wait_group 2;\n" ::: "memory");
        else if (rem == 1) asm volatile("cp.async.wait_group 1;\n" ::: "memory");
        else               asm volatile("cp.async.wait_group 0;\n" ::: "memory");
        __syncwarp();

        const float2* __restrict__ srow =
            (const float2*)(wsm + (tt % STAGES) * TILE_FLOATS) + lane;

        // 4-deep LDS.64 lookahead (> 29-cyc LDS latency)
        float2 xv0 = srow[0 * 32];
        float2 xv1 = srow[1 * 32];
        float2 xv2 = srow[2 * 32];
        float2 xv3 = srow[3 * 32];

        #pragma unroll
        for (int r = 0; r < U; r++) {
            float2 xn = (r + 4 < U) ? srow[(r + 4) * 32]
                                    : make_float2(0.0f, 0.0f);
            // two independent scan chains
            const float xiA  = xv0.x * weight;
            const float xiB  = xv0.y * weight;
            vs0 = fmaf(alpha, vs0, xiA);
            vs1 = fmaf(alpha, vs1, xiB);
            const float vmpA = fmaf(alpha, vm0, vs0);
            const float vmpB = fmaf(alpha, vm1, vs1);
            const bool  sA   = (vmpA >= 1.0f);
            const bool  sB   = (vmpB >= 1.0f);
            vm0 = sA ? (vmpA - 1.0f) : vmpA;
            vm1 = sB ? (vmpB - 1.0f) : vmpB;
            float2 sv;
            sv.x = sA ? 1.0f : 0.0f;
            sv.y = sB ? 1.0f : 0.0f;
            __stcs(oplane + (long)(tt * U + r) * (N_DIM / VEC), sv);
            xv0 = xv1; xv1 = xv2; xv2 = xv3; xv3 = xn;
        }

        __syncwarp();   // all lanes done with tile tt before its stage reuse
    }
}

extern "C" void kernel_launch(void* const* d_in, const int* in_sizes, int n_in,
                              void* d_out, int out_size) {
    const float* x = (const float*)d_in[0];
    const float* w = (const float*)d_in[1];
    float* out = (float*)d_out;

    // 128 blocks x 2 warps: <=1 block/SM, warps on distinct SMSPs.
    exodus_kernel<<<128, BLOCK>>>(x, w, out);
}

// round 6
// speedup vs baseline: 1.0786x; 1.0786x over previous
#include <cuda_runtime.h>
#include <cuda.h>
#include <cstdint>

// ExodusNeuron scan, R6: TMA in / TMA out, scan stays in registers.
// 256 single-warp blocks (R4 shape, 148-SM coverage). Per tile (64 steps):
//   - 1x UTMALDG 2D (16KB) into 3-stage smem ring, mbarrier complete_tx
//   - scan 64 steps from smem (LDS.64), spikes to smem out-ring (STS.64)
//   - 1x UTMASTG 2D (16KB) from 2-stage out ring, bulk_group
// Per-element numerics bit-exact vs reference (rel_err 0.0 R1-R5):
//   xi = x*w ; vs = fma(a,vs,xi) [packed f32x2, bit-identical]
//   vmp = fma(a,vm,vs) ; spk = vmp>=1 ; vm = spk ? vmp-1 : vmp

#define T_STEPS 2048
#define N_DIM   512
#define B_DIM   32
#define U       64
#define NT      (T_STEPS / U)          // 32 tiles
#define IN_STAGES  3
#define OUT_STAGES 2
#define NSEQ    64                     // sequences per warp (VEC=2 x 32 lanes)
#define TILE_FLOATS (U * NSEQ)         // 4096 floats = 16 KB
#define TILE_BYTES  (TILE_FLOATS * 4)
#define DYN_SMEM ((IN_STAGES + OUT_STAGES) * TILE_BYTES)   // 80 KB

// ---------------- PTX helpers ----------------
__device__ __forceinline__ uint32_t smem_u32(const void* p) {
    return (uint32_t)__cvta_generic_to_shared(p);
}
__device__ __forceinline__ void mbar_init(uint32_t a, uint32_t cnt) {
    asm volatile("mbarrier.init.shared.b64 [%0], %1;" :: "r"(a), "r"(cnt) : "memory");
}
__device__ __forceinline__ void mbar_expect_tx(uint32_t a, uint32_t bytes) {
    asm volatile("mbarrier.arrive.expect_tx.shared.b64 _, [%0], %1;"
                 :: "r"(a), "r"(bytes) : "memory");
}
__device__ __forceinline__ void mbar_wait(uint32_t a, uint32_t parity) {
    asm volatile(
        "{\n\t.reg .pred P;\n"
        "LW_%=:\n\t"
        "mbarrier.try_wait.parity.acquire.cta.shared::cta.b64 P, [%0], %1, 0x989680;\n\t"
        "@P bra LD_%=;\n\t"
        "bra LW_%=;\n"
        "LD_%=:\n\t}"
        :: "r"(a), "r"(parity) : "memory");
}
__device__ __forceinline__ void tma_load_2d(const void* map, uint32_t smem_dst,
                                            int cx, int cy, uint32_t mbar) {
    asm volatile(
        "cp.async.bulk.tensor.2d.shared::cta.global.tile.mbarrier::complete_tx::bytes "
        "[%0], [%1, {%2, %3}], [%4];"
        :: "r"(smem_dst), "l"(map), "r"(cx), "r"(cy), "r"(mbar) : "memory");
}
__device__ __forceinline__ void tma_store_2d(const void* map, int cx, int cy,
                                             uint32_t smem_src) {
    asm volatile(
        "cp.async.bulk.tensor.2d.global.shared::cta.tile.bulk_group "
        "[%0, {%1, %2}], [%3];"
        :: "l"(map), "r"(cx), "r"(cy), "r"(smem_src) : "memory");
}
__device__ __forceinline__ void fence_proxy_async_smem() {
    asm volatile("fence.proxy.async.shared::cta;" ::: "memory");
}
__device__ __forceinline__ uint64_t pk2(float a, float b) {
    uint64_t r; asm("mov.b64 %0, {%1, %2};" : "=l"(r) : "f"(a), "f"(b)); return r;
}
__device__ __forceinline__ void upk2(uint64_t v, float& a, float& b) {
    asm("mov.b64 {%0, %1}, %2;" : "=f"(a), "=f"(b) : "l"(v));
}
__device__ __forceinline__ uint64_t mul2(uint64_t a, uint64_t b) {
    uint64_t d; asm("mul.rn.f32x2 %0, %1, %2;" : "=l"(d) : "l"(a), "l"(b)); return d;
}
__device__ __forceinline__ uint64_t fma2(uint64_t a, uint64_t b, uint64_t c) {
    uint64_t d; asm("fma.rn.f32x2 %0, %1, %2, %3;" : "=l"(d) : "l"(a), "l"(b), "l"(c)); return d;
}

// ---------------- main kernel (TMA) ----------------
__global__ __launch_bounds__(32)
void exodus_tma_kernel(const __grid_constant__ CUtensorMap in_map,
                       const __grid_constant__ CUtensorMap out_map,
                       const float* __restrict__ w) {
    extern __shared__ __align__(128) char dsm[];
    float* in_tiles  = (float*)dsm;                                // 3 x 16 KB
    float* out_tiles = (float*)(dsm + IN_STAGES * TILE_BYTES);     // 2 x 16 KB
    __shared__ __align__(8) unsigned long long mbar_s[IN_STAGES];

    const int lane = threadIdx.x;
    const int b    = blockIdx.x >> 3;
    const int n0   = (blockIdx.x & 7) * NSEQ;
    const int row0 = b * T_STEPS;

    uint32_t mbar[IN_STAGES];
    #pragma unroll
    for (int s = 0; s < IN_STAGES; s++) mbar[s] = smem_u32(&mbar_s[s]);

    if (lane == 0) {
        #pragma unroll
        for (int s = 0; s < IN_STAGES; s++) mbar_init(mbar[s], 1);
    }
    __syncwarp();

    const float weight = w[0];
    const float alpha  = 0.95122942450071400910f;   // exp(-1/20) as f32
    const uint64_t w2  = pk2(weight, weight);
    const uint64_t a2  = pk2(alpha, alpha);

    auto issue_load = [&](int tt) {
        if (lane == 0) {
            const int s = tt % IN_STAGES;
            mbar_expect_tx(mbar[s], TILE_BYTES);
            tma_load_2d(&in_map, smem_u32(in_tiles + s * TILE_FLOATS),
                        n0, row0 + tt * U, mbar[s]);
        }
    };
    issue_load(0);
    issue_load(1);

    uint64_t vs2 = 0;                 // packed (vsA, vsB) = (0,0)
    float vmA = 0.0f, vmB = 0.0f;

    for (int tt = 0; tt < NT; tt++) {
        if (tt + 2 < NT) issue_load(tt + 2);

        mbar_wait(mbar[tt % IN_STAGES], (tt / IN_STAGES) & 1);

        // out-stage reuse: allow at most 1 outstanding TMA store
        if (lane == 0)
            asm volatile("cp.async.bulk.wait_group 1;" ::: "memory");
        __syncwarp();

        const uint64_t* __restrict__ srow =
            (const uint64_t*)(in_tiles + (tt % IN_STAGES) * TILE_FLOATS) + lane;
        float2* __restrict__ orow =
            (float2*)(out_tiles + (tt & 1) * TILE_FLOATS) + lane;

        // 4-deep LDS.64 lookahead (> 29-cyc LDS latency)
        uint64_t xv0 = srow[0 * 32];
        uint64_t xv1 = srow[1 * 32];
        uint64_t xv2 = srow[2 * 32];
        uint64_t xv3 = srow[3 * 32];

        #pragma unroll
        for (int r = 0; r < U; r++) {
            uint64_t xn = (r + 4 < U) ? srow[(r + 4) * 32] : 0ull;
            const uint64_t xi2 = mul2(xv0, w2);      // x*w  (packed, bit-exact)
            vs2 = fma2(a2, vs2, xi2);                // ExpLeak (packed)
            float vsA, vsB; upk2(vs2, vsA, vsB);
            const float vmpA = fmaf(alpha, vmA, vsA);
            const float vmpB = fmaf(alpha, vmB, vsB);
            const bool  sA = (vmpA >= 1.0f);
            const bool  sB = (vmpB >= 1.0f);
            vmA = sA ? (vmpA - 1.0f) : vmpA;
            vmB = sB ? (vmpB - 1.0f) : vmpB;
            float2 sv;
            sv.x = sA ? 1.0f : 0.0f;
            sv.y = sB ? 1.0f : 0.0f;
            orow[r * 32] = sv;                       // STS.64
            xv0 = xv1; xv1 = xv2; xv2 = xv3; xv3 = xn;
        }

        __syncwarp();
        if (lane == 0) {
            fence_proxy_async_smem();
            tma_store_2d(&out_map, n0, row0 + tt * U,
                         smem_u32(out_tiles + (tt & 1) * TILE_FLOATS));
            asm volatile("cp.async.bulk.commit_group;" ::: "memory");
        }
    }

    if (lane == 0)
        asm volatile("cp.async.bulk.wait_group 0;" ::: "memory");
}

// ---------------- fallback kernel (R4, proven 39.6us) ----------------
__device__ __forceinline__ void cp_async16(uint32_t saddr, const void* gaddr) {
    asm volatile("cp.async.cg.shared.global [%0], [%1], 16;\n" :: "r"(saddr), "l"(gaddr));
}
__global__ __launch_bounds__(32)
void exodus_fallback(const float* __restrict__ x, const float* __restrict__ w,
                     float* __restrict__ out) {
    __shared__ float smem[IN_STAGES * TILE_FLOATS];
    const int tid = threadIdx.x;
    const int b   = blockIdx.x >> 3;
    const int n0  = (blockIdx.x & 7) * NSEQ;
    const float weight = w[0];
    const float alpha  = 0.95122942450071400910f;
    const long gbase = (long)b * (T_STEPS * N_DIM) + n0;
    const float* __restrict__ xblk = x + gbase;
    float2* __restrict__ oplane = (float2*)(out + gbase) + tid;
    const uint32_t sbase = smem_u32(smem);
    const int chunkCol = tid & 15, rowOff = tid >> 4;
    auto issue_tile = [&](int tt) {
        const uint32_t s0 = sbase + (tt % IN_STAGES) * TILE_BYTES + rowOff * 256 + chunkCol * 16;
        const float* g0 = xblk + (long)(tt * U + rowOff) * N_DIM + chunkCol * 4;
        #pragma unroll
        for (int i = 0; i < U / 2; i++)
            cp_async16(s0 + i * 2 * 256, g0 + (long)i * 2 * N_DIM);
        asm volatile("cp.async.commit_group;\n" ::: "memory");
    };
    issue_tile(0); issue_tile(1);
    float vs0 = 0, vm0 = 0, vs1 = 0, vm1 = 0;
    for (int tt = 0; tt < NT; tt++) {
        if (tt + 2 < NT) issue_tile(tt + 2);
        const int rem = NT - 1 - tt;
        if      (rem >= 2) asm volatile("cp.async.wait_group 2;\n" ::: "memory");
        else if (rem == 1) asm volatile("cp.async.wait_group 1;\n" ::: "memory");
        else               asm volatile("cp.async.wait_group 0;\n" ::: "memory");
        __syncwarp();
        const float2* __restrict__ srow =
            (const float2*)(smem + (tt % IN_STAGES) * TILE_FLOATS) + tid;
        float2 xv0 = srow[0], xv1 = srow[32], xv2 = srow[64], xv3 = srow[96];
        #pragma unroll
        for (int r = 0; r < U; r++) {
            float2 xn = (r + 4 < U) ? srow[(r + 4) * 32] : make_float2(0.f, 0.f);
            const float xiA = xv0.x * weight, xiB = xv0.y * weight;
            vs0 = fmaf(alpha, vs0, xiA); vs1 = fmaf(alpha, vs1, xiB);
            const float vmpA = fmaf(alpha, vm0, vs0), vmpB = fmaf(alpha, vm1, vs1);
            const bool sA = (vmpA >= 1.f), sB = (vmpB >= 1.f);
            vm0 = sA ? (vmpA - 1.f) : vmpA; vm1 = sB ? (vmpB - 1.f) : vmpB;
            float2 sv; sv.x = sA ? 1.f : 0.f; sv.y = sB ? 1.f : 0.f;
            __stcs(oplane + (long)(tt * U + r) * (N_DIM / 2), sv);
            xv0 = xv1; xv1 = xv2; xv2 = xv3; xv3 = xn;
        }
        __syncwarp();
    }
}

// ---------------- host ----------------
typedef CUresult (*EncFn)(CUtensorMap*, CUtensorMapDataType, cuuint32_t, void*,
                          const cuuint64_t*, const cuuint64_t*, const cuuint32_t*,
                          const cuuint32_t*, CUtensorMapInterleave, CUtensorMapSwizzle,
                          CUtensorMapL2promotion, CUtensorMapFloatOOBfill);

extern "C" void kernel_launch(void* const* d_in, const int* in_sizes, int n_in,
                              void* d_out, int out_size) {
    const float* x = (const float*)d_in[0];
    const float* w = (const float*)d_in[1];
    float* out = (float*)d_out;

    EncFn enc = nullptr;
    cudaDriverEntryPointQueryResult qr = cudaDriverEntryPointSymbolNotFound;
    cudaGetDriverEntryPointByVersion("cuTensorMapEncodeTiled", (void**)&enc,
                                     12000, cudaEnableDefault, &qr);

    bool ok = (enc != nullptr) && (qr == cudaDriverEntryPointSuccess);
    CUtensorMap in_map, out_map;
    if (ok) {
        cuuint64_t dims[2]    = {N_DIM, (cuuint64_t)B_DIM * T_STEPS};
        cuuint64_t strides[1] = {N_DIM * sizeof(float)};
        cuuint32_t box[2]     = {NSEQ, U};          // 64 floats (256B) x 64 rows
        cuuint32_t es[2]      = {1, 1};
        ok = (enc(&in_map, CU_TENSOR_MAP_DATA_TYPE_FLOAT32, 2, (void*)x,
                  dims, strides, box, es,
                  CU_TENSOR_MAP_INTERLEAVE_NONE, CU_TENSOR_MAP_SWIZZLE_NONE,
                  CU_TENSOR_MAP_L2_PROMOTION_L2_128B,
                  CU_TENSOR_MAP_FLOAT_OOB_FILL_NONE) == CUDA_SUCCESS)
          && (enc(&out_map, CU_TENSOR_MAP_DATA_TYPE_FLOAT32, 2, (void*)out,
                  dims, strides, box, es,
                  CU_TENSOR_MAP_INTERLEAVE_NONE, CU_TENSOR_MAP_SWIZZLE_NONE,
                  CU_TENSOR_MAP_L2_PROMOTION_L2_128B,
                  CU_TENSOR_MAP_FLOAT_OOB_FILL_NONE) == CUDA_SUCCESS);
    }

    if (ok) {
        cudaFuncSetAttribute(exodus_tma_kernel,
                             cudaFuncAttributeMaxDynamicSharedMemorySize, DYN_SMEM);
        exodus_tma_kernel<<<256, 32, DYN_SMEM>>>(in_map, out_map, w);
    } else {
        exodus_fallback<<<256, 32>>>(x, w, out);
    }
}

// round 7
// speedup vs baseline: 1.0889x; 1.0095x over previous
#include <cuda_runtime.h>
#include <cstdint>

// ExodusNeuron scan, R7: compute made sub-dominant to DRAM.
// 128 blocks x 4 warps (one block/SM, warp w -> SMSP w), VEC=1: 32 seqs/warp.
// Each warp fully independent: private 3-stage cp.async ring (8KB tiles,
// prefetch distance 2), private commit groups, __syncwarp only.
// Per-warp compute ~26k cyc (~15us) << DRAM floor (~32us) -> DRAM-bound.
//
// Numerics bit-exact vs reference (rel_err 0.0 in R1-R6):
//   xi = x*w ; vs = fma(a,vs,xi) ; vmp = fma(a,vm,vs)
//   spk = vmp >= 1 ; vm = spk ? vmp-1 : vmp

#define T_STEPS 2048
#define N_DIM   512
#define WARPS   4
#define BLOCK   (WARPS * 32)
#define U       64                       // time-steps per tile
#define NT      (T_STEPS / U)            // 32 tiles
#define STAGES  3
#define TILE_FLOATS (U * 32)             // 2048 floats = 8 KB per warp-tile
#define TILE_BYTES  (TILE_FLOATS * 4)
#define WARP_SMEM_F (STAGES * TILE_FLOATS)
#define DYN_SMEM    (WARPS * WARP_SMEM_F * 4)   // 96 KB

__device__ __forceinline__ void cp_async16(uint32_t saddr, const void* gaddr) {
    asm volatile("cp.async.cg.shared.global [%0], [%1], 16;\n"
                 :: "r"(saddr), "l"(gaddr));
}
__device__ __forceinline__ void cp_commit() {
    asm volatile("cp.async.commit_group;\n" ::: "memory");
}

__global__ __launch_bounds__(BLOCK)
void exodus_kernel(const float* __restrict__ x,
                   const float* __restrict__ w,
                   float* __restrict__ out) {
    extern __shared__ __align__(16) float smem[];   // 96 KB dynamic

    const int tid  = threadIdx.x;
    const int wid  = tid >> 5;
    const int lane = tid & 31;

    const int b  = blockIdx.x >> 2;                      // 32 batches
    const int n0 = (blockIdx.x & 3) * 128 + wid * 32;    // warp's 32 seqs

    const float weight = w[0];
    const float alpha  = 0.95122942450071400910f;   // exp(-1/20) as f32

    const long gbase = (long)b * (T_STEPS * N_DIM) + n0;
    const float* __restrict__ xblk = x + gbase;          // warp's column base
    float* __restrict__ oplane = out + gbase + lane;

    float* const wsm = smem + wid * WARP_SMEM_F;
    const uint32_t sbase = (uint32_t)__cvta_generic_to_shared(wsm);

    // Loader: one row (time-step) = 32 floats = 128 B = 8 x 16 B chunks.
    // chunkCol = lane & 7 spans a row; rowOff = lane >> 3 staggers 4 rows.
    const int chunkCol = lane & 7;
    const int rowOff   = lane >> 3;

    auto issue_tile = [&](int tt) {
        const uint32_t s0 = sbase + (tt % STAGES) * TILE_BYTES
                          + rowOff * 128 + chunkCol * 16;
        const float* g0 = xblk + (long)(tt * U + rowOff) * N_DIM + chunkCol * 4;
        #pragma unroll
        for (int i = 0; i < U / 4; i++)                  // 16 x LDGSTS.128
            cp_async16(s0 + i * 4 * 128, g0 + (long)i * 4 * N_DIM);
        cp_commit();
    };

    issue_tile(0);
    issue_tile(1);

    float vs = 0.0f, vm = 0.0f;

    for (int tt = 0; tt < NT; tt++) {
        if (tt + 2 < NT) issue_tile(tt + 2);

        const int rem = NT - 1 - tt;
        if      (rem >= 2) asm volatile("cp.async.wait_group 2;\n" ::: "memory");
        else if (rem == 1) asm volatile("cp.async.wait_group 1;\n" ::: "memory");
        else               asm volatile("cp.async.wait_group 0;\n" ::: "memory");
        __syncwarp();

        const float* __restrict__ srow =
            wsm + (tt % STAGES) * TILE_FLOATS + lane;

        // 4-deep LDS.32 lookahead (48 cyc ahead > 29-cyc LDS latency)
        float xv0 = srow[0 * 32];
        float xv1 = srow[1 * 32];
        float xv2 = srow[2 * 32];
        float xv3 = srow[3 * 32];

        #pragma unroll
        for (int r = 0; r < U; r++) {
            float xn = (r + 4 < U) ? srow[(r + 4) * 32] : 0.0f;
            const float xi  = xv0 * weight;          // x*w rounded first
            vs = fmaf(alpha, vs, xi);                // ExpLeak
            const float vmp = fmaf(alpha, vm, vs);   // LIF integrate
            const bool  s   = (vmp >= 1.0f);
            vm = s ? (vmp - 1.0f) : vmp;             // FSEL, parallel w/ compare
            __stcs(oplane + (long)(tt * U + r) * N_DIM, s ? 1.0f : 0.0f);
            xv0 = xv1; xv1 = xv2; xv2 = xv3; xv3 = xn;
        }

        __syncwarp();   // all lanes past tile tt before its stage is reissued
    }
}

extern "C" void kernel_launch(void* const* d_in, const int* in_sizes, int n_in,
                              void* d_out, int out_size) {
    const float* x = (const float*)d_in[0];
    const float* w = (const float*)d_in[1];
    float* out = (float*)d_out;

    cudaFuncSetAttribute(exodus_kernel,
                         cudaFuncAttributeMaxDynamicSharedMemorySize, DYN_SMEM);
    // 128 blocks x 4 warps: 1 block/SM, each warp on its own SMSP,
    // 512 fully independent warps, 32 seqs each.
    exodus_kernel<<<128, BLOCK, DYN_SMEM>>>(x, w, out);
}